// round 2
// baseline (speedup 1.0000x reference)
#include <cuda_runtime.h>
#include <math.h>

// Problem constants
#define L_OBS   512
#define NSEG    8192
#define NPOSE   8
#define EPS_PAR 1.0e-4f

// Decomposition
#define SB        64            // segment slice-blocks per pose
#define SEGS_PER  (NSEG / SB)   // 128 segments per block
#define THREADS1  256           // 256 threads -> 2 beams each (512 beams)
#define TOTAL_BEAMS (NPOSE * L_OBS)  // 4096

// Static scratch for per-slice partial minima: (bn, bd) positive rational.
__device__ float2 g_partial[SB * TOTAL_BEAMS];   // 2 MB

typedef unsigned long long ull;

__device__ __forceinline__ ull pack2(float lo, float hi) {
    ull r;
    asm("mov.b64 %0, {%1, %2};" : "=l"(r) : "f"(lo), "f"(hi));
    return r;
}
__device__ __forceinline__ void unpack2(ull v, float& lo, float& hi) {
    asm("mov.b64 {%0, %1}, %2;" : "=f"(lo), "=f"(hi) : "l"(v));
}
__device__ __forceinline__ ull mul2(ull a, ull b) {
    ull r;
    asm("mul.rn.f32x2 %0, %1, %2;" : "=l"(r) : "l"(a), "l"(b));
    return r;
}
__device__ __forceinline__ ull fma2(ull a, ull b, ull c) {
    ull r;
    asm("fma.rn.f32x2 %0, %1, %2, %3;" : "=l"(r) : "l"(a), "l"(b), "l"(c));
    return r;
}

__device__ __forceinline__ float beam_angle(int i, float th) {
    const float step = (float)(6.283185307179586 / 512.0);
    return (float)i * step + th;
}

// Scalar validity + running-min update for one beam.
// Conditions (all as sign tests, no division):
//   u_a >= 0     <=>  sign(num_a) == sign(rxs)
//   u_b >= 0     <=>  sign(num_b) == sign(rxs)
//   u_b <= 1     <=>  sign(num_b - rxs) != sign(rxs)
// Running min kept as positive rational (bn, bd); compare by cross-multiply.
__device__ __forceinline__ void beam_update(
    int naI, float anaF, float nb, float rxs, float c,
    float& bn, float& bd)
{
    int r = __float_as_int(rxs);
    int m = (naI ^ r) | (__float_as_int(nb) ^ r) | (__float_as_int(c) ^ ~r);
    float ad = fabsf(rxs);
    float q1 = anaF * bd;
    float q2 = bn * ad;
    bool ok = (m >= 0) & (ad >= EPS_PAR) & (q1 < q2);
    if (ok) { bn = anaF; bd = ad; }
}

__global__ __launch_bounds__(THREADS1)
void sense_partial_kernel(const float* __restrict__ line_seg,
                          const float* __restrict__ pose)
{
    const int sb = blockIdx.x;           // segment slice
    const int b  = blockIdx.y;           // pose
    const float x1 = pose[b * 3 + 0];
    const float y1 = pose[b * 3 + 1];
    const float th = pose[b * 3 + 2];

    // Pre-duplicated packed tiles: each 64-bit word is (v, v).
    __shared__ ulonglong2 sA[SEGS_PER];  // (x13,x13), (y13,y13)
    __shared__ ulonglong2 sB[SEGS_PER];  // (sx,sx),   (sy,sy)
    __shared__ uint2      sC[SEGS_PER];  // bits(|na|), bits(na)

    const int tid = threadIdx.x;

    for (int s = tid; s < SEGS_PER; s += THREADS1) {
        float4 seg = reinterpret_cast<const float4*>(line_seg)[sb * SEGS_PER + s];
        float sx  = seg.z - seg.x;
        float sy  = seg.w - seg.y;
        float x13 = x1 - seg.x;
        float y13 = y1 - seg.y;
        float na  = sx * y13 - sy * x13;
        sA[s] = make_ulonglong2(pack2(x13, x13), pack2(y13, y13));
        sB[s] = make_ulonglong2(pack2(sx, sx),   pack2(sy, sy));
        sC[s] = make_uint2(__float_as_uint(fabsf(na)), __float_as_uint(na));
    }
    __syncthreads();

    // Two beams per thread: A = tid, B = tid + 256. Beam A in lane .lo.
    const int beamA = tid;
    const int beamB = tid + THREADS1;
    float angA = beam_angle(beamA, th);
    float angB = beam_angle(beamB, th);
    float rxA = cosf(angA), ryA = sinf(angA);
    float rxB = cosf(angB), ryB = sinf(angB);

    const ull rx2   = pack2(rxA, rxB);
    const ull nry2  = pack2(-ryA, -ryB);     // negated ry, hoists negation
    const ull neg1  = pack2(-1.0f, -1.0f);

    const float INF = __int_as_float(0x7f800000);
    float bnA = INF, bdA = 1.0f;
    float bnB = INF, bdB = 1.0f;

    #pragma unroll 4
    for (int s = 0; s < SEGS_PER; s++) {
        ulonglong2 a  = sA[s];
        ulonglong2 bq = sB[s];
        uint2      cc = sC[s];

        // num_b = rx*y13 - ry*x13 ; rxs = sy*rx - sx*ry ; c = num_b - rxs
        ull t1   = mul2(nry2, a.x);               // -ry * x13
        ull nb2  = fma2(rx2,  a.y, t1);           //  rx * y13 - ry*x13
        ull t2   = mul2(nry2, bq.x);              // -ry * sx
        ull rxs2 = fma2(rx2,  bq.y, t2);          //  rx * sy - ry*sx
        ull c2   = fma2(rxs2, neg1, nb2);         //  num_b - rxs

        float nbA, nbB, rxsA, rxsB, cA, cB;
        unpack2(nb2,  nbA,  nbB);
        unpack2(rxs2, rxsA, rxsB);
        unpack2(c2,   cA,   cB);

        float anaF = __uint_as_float(cc.x);
        int   naI  = (int)cc.y;

        beam_update(naI, anaF, nbA, rxsA, cA, bnA, bdA);
        beam_update(naI, anaF, nbB, rxsB, cB, bnB, bdB);
    }

    const int base = b * L_OBS;
    g_partial[sb * TOTAL_BEAMS + base + beamA] = make_float2(bnA, bdA);
    g_partial[sb * TOTAL_BEAMS + base + beamB] = make_float2(bnB, bdB);
}

__global__ __launch_bounds__(256)
void reduce_final_kernel(const float* __restrict__ line_seg,
                         const float* __restrict__ pose,
                         float* __restrict__ out)
{
    const int g = blockIdx.x * blockDim.x + threadIdx.x;   // 0..4095
    if (g >= TOTAL_BEAMS) return;
    const int b = g >> 9;          // /512
    const int l = g & (L_OBS - 1);

    const float INF = __int_as_float(0x7f800000);
    float bn = INF, bd = 1.0f;
    #pragma unroll 16
    for (int sb = 0; sb < SB; sb++) {
        float2 p = g_partial[sb * TOTAL_BEAMS + g];
        if (p.x * bd < bn * p.y) { bn = p.x; bd = p.y; }
    }

    const float x1 = pose[b * 3 + 0];
    const float y1 = pose[b * 3 + 1];
    const float th = pose[b * 3 + 2];
    float ang = beam_angle(l, th);
    float rx = cosf(ang), ry = sinf(ang);

    float u;
    if (bn < INF) {
        u = bn / bd;
    } else {
        // No valid hit anywhere: argmin of all-inf picks index 0 -> u_a[seg 0]
        float x3 = line_seg[0], y3 = line_seg[1];
        float x4 = line_seg[2], y4 = line_seg[3];
        float sx = x4 - x3, sy = y4 - y3;
        float x13 = x1 - x3, y13 = y1 - y3;
        float rxs = sy * rx - sx * ry;
        float na  = sx * y13 - sy * x13;
        u = (fabsf(rxs) < EPS_PAR) ? 0.0f : (na / rxs);
    }

    float ix = x1 + rx * u;
    float iy = y1 + ry * u;

    // obs_global
    out[2 * g + 0] = ix;
    out[2 * g + 1] = iy;

    // obs_local = (obs_global - c0) @ R,  R = [[c,-s],[s,c]]
    float dx = ix - x1;
    float dy = iy - y1;
    float ct = cosf(th), st = sinf(th);
    out[2 * TOTAL_BEAMS + 2 * g + 0] =  dx * ct + dy * st;
    out[2 * TOTAL_BEAMS + 2 * g + 1] = -dx * st + dy * ct;
}

extern "C" void kernel_launch(void* const* d_in, const int* in_sizes, int n_in,
                              void* d_out, int out_size)
{
    const float* line_seg = (const float*)d_in[0];   // (8192, 4)
    const float* pose     = (const float*)d_in[1];   // (8, 3)
    float* out = (float*)d_out;                      // 16384 floats

    dim3 grid1(SB, NPOSE);
    sense_partial_kernel<<<grid1, THREADS1>>>(line_seg, pose);
    reduce_final_kernel<<<TOTAL_BEAMS / 256, 256>>>(line_seg, pose, out);
}

// round 15
// speedup vs baseline: 1.4885x; 1.4885x over previous
#include <cuda_runtime.h>
#include <math.h>

// Problem constants
#define L_OBS   512
#define NSEG    8192
#define NPOSE   8
#define EPS_PAR 1.0e-4f

#define STEP      0.012271846644580364f   // 2*pi/512
#define TWO_PI    6.2831853071795864f
#define INV_2PI   0.15915494309189535f
// warp cone half-width (31.5 beams) + conservative margin
#define WH_TOT    (31.5f * STEP + 0.01f)

// Decomposition
#define SB        64            // segment slice-blocks per pose
#define SEGS_PER  (NSEG / SB)   // 128 segments per block
#define THREADS1  256           // 256 threads -> 2 adjacent beams each
#define TOTAL_BEAMS (NPOSE * L_OBS)  // 4096

// Partial minima, transposed: logical layout float2 p[beam][sb] (64 contiguous
// float2 per beam). Declared as float4 so the reduce kernel's 128-bit loads
// are guaranteed 16B-aligned; sense stores through a float2 view.
__device__ float4 g_partial4[TOTAL_BEAMS * SB / 2];   // 2 MB

typedef unsigned long long ull;

__device__ __forceinline__ ull pack2(float lo, float hi) {
    ull r; asm("mov.b64 %0, {%1, %2};" : "=l"(r) : "f"(lo), "f"(hi)); return r;
}
__device__ __forceinline__ void unpack2(ull v, float& lo, float& hi) {
    asm("mov.b64 {%0, %1}, %2;" : "=f"(lo), "=f"(hi) : "l"(v));
}
__device__ __forceinline__ ull mul2(ull a, ull b) {
    ull r; asm("mul.rn.f32x2 %0, %1, %2;" : "=l"(r) : "l"(a), "l"(b)); return r;
}
__device__ __forceinline__ ull fma2(ull a, ull b, ull c) {
    ull r; asm("fma.rn.f32x2 %0, %1, %2, %3;" : "=l"(r) : "l"(a), "l"(b), "l"(c)); return r;
}

__device__ __forceinline__ float beam_angle(int i, float th) {
    return (float)i * STEP + th;
}

// Validity + running-min update (sign tests + cross-multiplied rational min).
//   u_a >= 0  <=>  sign(num_a) == sign(rxs)
//   u_b >= 0  <=>  sign(num_b) == sign(rxs)
//   u_b <= 1  <=>  sign(num_b - rxs) != sign(rxs)
__device__ __forceinline__ void beam_update(
    int naI, float anaF, float nb, float rxs, float c,
    float& bn, float& bd)
{
    int r = __float_as_int(rxs);
    int m = (naI ^ r) | (__float_as_int(nb) ^ r) | (__float_as_int(c) ^ ~r);
    float ad = fabsf(rxs);
    float q1 = anaF * bd;
    float q2 = bn * ad;
    bool ok = (m >= 0) & (ad >= EPS_PAR) & (q1 < q2);
    if (ok) { bn = anaF; bd = ad; }
}

// ---------------------------------------------------------------------------
__global__ __launch_bounds__(THREADS1)
void sense_partial_kernel(const float* __restrict__ line_seg,
                          const float* __restrict__ pose)
{
    const int sb = blockIdx.x;           // segment slice
    const int b  = blockIdx.y;           // pose
    const float x1 = pose[b * 3 + 0];
    const float y1 = pose[b * 3 + 1];
    const float th = pose[b * 3 + 2];

    __shared__ ulonglong2 sA[SEGS_PER];  // (x13,x13), (y13,y13)
    __shared__ ulonglong2 sB[SEGS_PER];  // (sx,sx),   (sy,sy)
    __shared__ uint2      sC[SEGS_PER];  // bits(|na|), bits(na)
    __shared__ float4     sArc[SEGS_PER];// cos c, sin c, cos(arcHalf+coneHalf+margin)

    const int tid  = threadIdx.x;
    const int lane = tid & 31;
    const int w    = tid >> 5;           // warp 0..7 -> beams [64w, 64w+64)

    // Prep: geometry + angular arc for each of this block's 128 segments.
    // Each (pose, seg) arc is used by exactly this one block -> computed inline.
    for (int s = tid; s < SEGS_PER; s += THREADS1) {
        float4 seg = reinterpret_cast<const float4*>(line_seg)[sb * SEGS_PER + s];
        float sx  = seg.z - seg.x;
        float sy  = seg.w - seg.y;
        float x13 = x1 - seg.x;
        float y13 = y1 - seg.y;
        float na  = sx * y13 - sy * x13;
        sA[s] = make_ulonglong2(pack2(x13, x13), pack2(y13, y13));
        sB[s] = make_ulonglong2(pack2(sx, sx),   pack2(sy, sy));
        sC[s] = make_uint2(__float_as_uint(fabsf(na)), __float_as_uint(na));

        // Directions from pose to endpoints: (-x13,-y13) and (seg.zw - pose).
        float a3 = atan2f(-y13, -x13);
        float a4 = atan2f(seg.w - y1, seg.z - x1);
        float d  = a4 - a3;
        d -= TWO_PI * rintf(d * INV_2PI);     // wrap to (-pi, pi]
        float c  = a3 + 0.5f * d;             // short-arc center
        float hh = 0.5f * fabsf(d) + WH_TOT;  // <= pi/2 + ~0.4 < pi
        sArc[s] = make_float4(cosf(c), sinf(c), cosf(hh), 0.0f);
    }
    __syncthreads();

    // Adjacent beams per thread: A = 2*tid, B = 2*tid+1.
    const int beamA = 2 * tid;
    float angA = beam_angle(beamA, th);
    float angB = angA + STEP;
    float rxA = cosf(angA), ryA = sinf(angA);
    float rxB = cosf(angB), ryB = sinf(angB);

    const ull rx2   = pack2(rxA, rxB);
    const ull nry2  = pack2(-ryA, -ryB);
    const ull neg1  = pack2(-1.0f, -1.0f);

    // Warp cone center unit vector (uniform across the warp).
    float wc = th + (64.0f * (float)w + 31.5f) * STEP;
    float wx = cosf(wc), wy = sinf(wc);

    const float INF = __int_as_float(0x7f800000);
    float bnA = INF, bdA = 1.0f;
    float bnB = INF, bdB = 1.0f;

    for (int s0 = 0; s0 < SEGS_PER; s0 += 32) {
        // Each lane culls one segment; survivors compacted via ballot.
        float4 arc = sArc[s0 + lane];
        bool hit = (wx * arc.x + wy * arc.y >= arc.z);
        unsigned m = __ballot_sync(0xffffffffu, hit);
        while (m) {                       // warp-uniform loop (m uniform)
            int s = s0 + (__ffs(m) - 1);
            m &= m - 1;

            ulonglong2 a  = sA[s];
            ulonglong2 bq = sB[s];
            uint2      cc = sC[s];

            // num_b = rx*y13 - ry*x13 ; rxs = sy*rx - sx*ry ; c = num_b - rxs
            ull t1   = mul2(nry2, a.x);
            ull nb2  = fma2(rx2,  a.y, t1);
            ull t2   = mul2(nry2, bq.x);
            ull rxs2 = fma2(rx2,  bq.y, t2);
            ull c2   = fma2(rxs2, neg1, nb2);

            float nbA, nbB, rxsA, rxsB, cA, cB;
            unpack2(nb2,  nbA,  nbB);
            unpack2(rxs2, rxsA, rxsB);
            unpack2(c2,   cA,   cB);

            float anaF = __uint_as_float(cc.x);
            int   naI  = (int)cc.y;

            beam_update(naI, anaF, nbA, rxsA, cA, bnA, bdA);
            beam_update(naI, anaF, nbB, rxsB, cB, bnB, bdB);
        }
    }

    float2* gp = reinterpret_cast<float2*>(g_partial4);
    const int base = b * L_OBS;
    gp[(base + beamA)     * SB + sb] = make_float2(bnA, bdA);
    gp[(base + beamA + 1) * SB + sb] = make_float2(bnB, bdB);
}

// ---------------------------------------------------------------------------
// Warp-per-beam reduction: lane l combines partials sb=2l,2l+1 (one LDG.128,
// coalesced 512B per warp), then a shfl tree; lane 0 runs the epilogue.
__global__ __launch_bounds__(256)
void reduce_final_kernel(const float* __restrict__ line_seg,
                         const float* __restrict__ pose,
                         float* __restrict__ out)
{
    const int warp = blockIdx.x * (blockDim.x >> 5) + (threadIdx.x >> 5);
    const int lane = threadIdx.x & 31;
    const int g = warp;                  // beam id 0..4095 (grid covers exactly)
    const int b = g >> 9;
    const int l = g & (L_OBS - 1);

    float4 v = g_partial4[g * (SB / 2) + lane];
    float bn = v.x, bd = v.y;
    if (v.z * bd < bn * v.w) { bn = v.z; bd = v.w; }

    #pragma unroll
    for (int d = 16; d >= 1; d >>= 1) {
        float on = __shfl_down_sync(0xffffffffu, bn, d);
        float od = __shfl_down_sync(0xffffffffu, bd, d);
        if (on * bd < bn * od) { bn = on; bd = od; }
    }

    if (lane == 0) {
        const float INF = __int_as_float(0x7f800000);
        const float x1 = pose[b * 3 + 0];
        const float y1 = pose[b * 3 + 1];
        const float th = pose[b * 3 + 2];
        float ang = beam_angle(l, th);
        float rx = cosf(ang), ry = sinf(ang);

        float u;
        if (bn < INF) {
            u = bn / bd;
        } else {
            // No valid hit anywhere: argmin of all-inf picks index 0 -> u_a[seg 0]
            float x3 = line_seg[0], y3 = line_seg[1];
            float x4 = line_seg[2], y4 = line_seg[3];
            float sx = x4 - x3, sy = y4 - y3;
            float x13 = x1 - x3, y13 = y1 - y3;
            float rxs = sy * rx - sx * ry;
            float na  = sx * y13 - sy * x13;
            u = (fabsf(rxs) < EPS_PAR) ? 0.0f : (na / rxs);
        }

        float ix = x1 + rx * u;
        float iy = y1 + ry * u;

        out[2 * g + 0] = ix;
        out[2 * g + 1] = iy;

        float dx = ix - x1;
        float dy = iy - y1;
        float ct = cosf(th), st = sinf(th);
        out[2 * TOTAL_BEAMS + 2 * g + 0] =  dx * ct + dy * st;
        out[2 * TOTAL_BEAMS + 2 * g + 1] = -dx * st + dy * ct;
    }
}

extern "C" void kernel_launch(void* const* d_in, const int* in_sizes, int n_in,
                              void* d_out, int out_size)
{
    const float* line_seg = (const float*)d_in[0];   // (8192, 4)
    const float* pose     = (const float*)d_in[1];   // (8, 3)
    float* out = (float*)d_out;                      // 16384 floats

    dim3 grid1(SB, NPOSE);
    sense_partial_kernel<<<grid1, THREADS1>>>(line_seg, pose);
    reduce_final_kernel<<<TOTAL_BEAMS / 8, 256>>>(line_seg, pose, out);
}